// round 3
// baseline (speedup 1.0000x reference)
#include <cuda_runtime.h>
#include <cuda_bf16.h>
#include <cstddef>

#define DD 128
#define MAXN 100000
#define MAXE 1000000
#define WPAD 132   // smem row stride: %4==0 -> 16B-aligned rows for LDS.128; not %32 -> de-conflicted banks

// ---- scratch (no cudaMalloc allowed) ----
__device__ float g_aggr[(size_t)MAXN * DD];
__device__ float g_z1[(size_t)MAXN * DD];
__device__ float g_z2[(size_t)MAXN * DD];
__device__ int   g_idx[(size_t)2 * MAXE];   // canonical int32 edge list: [src(E), dst(E)]
__device__ int   g_fmt;                      // 1 = input was int64, 0 = int32
__device__ float g_sum[DD];
__device__ float g_sq[DD];
__device__ float g_s1[DD];
__device__ float g_c1[DD];
__device__ float g_sh[DD];
__device__ float g_ch[DD];

// ---------------------------------------------------------------- edge fmt detect
// If buffer holds int64 indices (< 2^31), every odd int32 word (little-endian high half) is 0.
__global__ void detect_kernel(const int* __restrict__ ei32, int E) {
    int allzero = 1;
    for (int k = 0; k < 64; k++) {
        long long e = (long long)(k + 1) * (2LL * E) / 66;  // spread samples
        if (ei32[2 * (e >> 1) + 1] != 0) { allzero = 0; break; }
    }
    g_fmt = allzero;
}

// canonicalize to int32, clamp defensively
__global__ void convert_kernel(const void* __restrict__ ei, int n2, int N) {
    int i = blockIdx.x * blockDim.x + threadIdx.x;
    if (i >= n2) return;
    int v;
    if (g_fmt) v = (int)((const long long*)ei)[i];
    else       v = ((const int*)ei)[i];
    if (v < 0) v = 0;
    if (v >= N) v = N - 1;
    g_idx[i] = v;
}

// ---------------------------------------------------------------- zero
__global__ void zero_kernel(float4* __restrict__ p, int n4) {
    int i = blockIdx.x * blockDim.x + threadIdx.x;
    if (i < n4) p[i] = make_float4(0.f, 0.f, 0.f, 0.f);
}

// ---------------------------------------------------------------- scatter
// mode 0: msg = relu(h[src])
// mode 1: msg = relu(sH*h[src]+cH)   (affine = prev outer BN; relu after affine)
__global__ void scatter_kernel(const float4* __restrict__ h,
                               const int* __restrict__ idx, int E,
                               float* __restrict__ aggr,
                               const float* __restrict__ sH,
                               const float* __restrict__ cH, int mode) {
    __shared__ float ss[DD], sc[DD];
    if (mode) {
        if (threadIdx.x < DD) { ss[threadIdx.x] = sH[threadIdx.x]; sc[threadIdx.x] = cH[threadIdx.x]; }
        __syncthreads();
    }
    int gt = blockIdx.x * blockDim.x + threadIdx.x;
    int e = gt >> 5;
    if (e >= E) return;
    int lane = gt & 31;
    int src = idx[e];
    int dst = idx[E + e];
    float4 v = h[(size_t)src * 32 + lane];
    int k = lane * 4;
    if (mode) {
        v.x = fmaf(ss[k + 0], v.x, sc[k + 0]);
        v.y = fmaf(ss[k + 1], v.y, sc[k + 1]);
        v.z = fmaf(ss[k + 2], v.z, sc[k + 2]);
        v.w = fmaf(ss[k + 3], v.w, sc[k + 3]);
    }
    v.x = fmaxf(v.x, 0.f); v.y = fmaxf(v.y, 0.f);
    v.z = fmaxf(v.z, 0.f); v.w = fmaxf(v.w, 0.f);
    float* o = aggr + (size_t)dst * DD + k;
    if (v.x != 0.f) atomicAdd(o + 0, v.x);
    if (v.y != 0.f) atomicAdd(o + 1, v.y);
    if (v.z != 0.f) atomicAdd(o + 2, v.z);
    if (v.w != 0.f) atomicAdd(o + 3, v.w);
}

// ---------------------------------------------------------------- GEMM
// out[row][j] = sum_k a(row,k) * W[j][k] + bias[j]
// mode 0: a = (1+eps)*h + aggr
// mode 1: a = (1+eps)*relu(sIn*h+cIn) + aggr
// mode 2: a = relu(sIn*h+cIn)
// Epilogue: write Z, accumulate per-feature sum & sumsq.
__global__ void __launch_bounds__(256, 2) gemm_kernel(
    const float* __restrict__ Ab, const float* __restrict__ aggr,
    const float* __restrict__ W, const float* __restrict__ bias,
    const float* __restrict__ sIn, const float* __restrict__ cIn,
    const float* __restrict__ epsP, int layer, int mode, int M,
    float* __restrict__ Z, float* __restrict__ gsum, float* __restrict__ gsq) {
    extern __shared__ float sm[];
    float* Ws = sm;                    // 128*WPAD (transposed: Ws[k*WPAD+j] = W[j][k])
    float* As = Ws + 128 * WPAD;       // 2 * 16 * WPAD
    float* csum = As + 2 * 16 * WPAD;  // 128
    float* csq = csum + DD;            // 128

    const int tid = threadIdx.x;
    for (int i = tid; i < DD * DD; i += 256) {
        int j = i >> 7, k = i & 127;
        Ws[k * WPAD + j] = W[i];
    }
    if (tid < DD) { csum[tid] = 0.f; csq[tid] = 0.f; }

    const int tx = tid & 15, ty = tid >> 4;
    const int rowBase = blockIdx.x << 7;
    const float ev = (mode == 2) ? 0.f : (1.0f + epsP[layer]);

    const int m0 = tid >> 2;
    const int kq = tid & 3;

    float acc[64];
#pragma unroll
    for (int i = 0; i < 64; i++) acc[i] = 0.f;

    float4 ra[2];

    auto loadChunk = [&](int c) {
        int kbase = c * 16 + kq * 4;
#pragma unroll
        for (int h2 = 0; h2 < 2; h2++) {
            int row = rowBase + m0 + h2 * 64;
            float4 v = make_float4(0.f, 0.f, 0.f, 0.f);
            if (row < M) {
                v = *(const float4*)(Ab + (size_t)row * DD + kbase);
                if (mode != 0) {
                    v.x = fmaxf(fmaf(sIn[kbase + 0], v.x, cIn[kbase + 0]), 0.f);
                    v.y = fmaxf(fmaf(sIn[kbase + 1], v.y, cIn[kbase + 1]), 0.f);
                    v.z = fmaxf(fmaf(sIn[kbase + 2], v.z, cIn[kbase + 2]), 0.f);
                    v.w = fmaxf(fmaf(sIn[kbase + 3], v.w, cIn[kbase + 3]), 0.f);
                }
                if (mode != 2) {
                    float4 g = *(const float4*)(aggr + (size_t)row * DD + kbase);
                    v.x = fmaf(ev, v.x, g.x); v.y = fmaf(ev, v.y, g.y);
                    v.z = fmaf(ev, v.z, g.z); v.w = fmaf(ev, v.w, g.w);
                }
            }
            ra[h2] = v;
        }
    };
    auto storeChunk = [&](int buf) {
        float* p = As + buf * (16 * WPAD);
#pragma unroll
        for (int h2 = 0; h2 < 2; h2++) {
            int m = m0 + h2 * 64;
            p[(kq * 4 + 0) * WPAD + m] = ra[h2].x;
            p[(kq * 4 + 1) * WPAD + m] = ra[h2].y;
            p[(kq * 4 + 2) * WPAD + m] = ra[h2].z;
            p[(kq * 4 + 3) * WPAD + m] = ra[h2].w;
        }
    };

    loadChunk(0);
    storeChunk(0);
    __syncthreads();

    for (int c = 0; c < 8; c++) {
        if (c < 7) loadChunk(c + 1);
        float* pA = As + (c & 1) * (16 * WPAD);
#pragma unroll
        for (int kk = 0; kk < 16; kk++) {
            float af[8], bf[8];
            *(float4*)(af)     = *(const float4*)(pA + kk * WPAD + ty * 8);
            *(float4*)(af + 4) = *(const float4*)(pA + kk * WPAD + ty * 8 + 4);
            int kg = c * 16 + kk;
            *(float4*)(bf)     = *(const float4*)(Ws + kg * WPAD + tx * 8);
            *(float4*)(bf + 4) = *(const float4*)(Ws + kg * WPAD + tx * 8 + 4);
#pragma unroll
            for (int i = 0; i < 8; i++)
#pragma unroll
                for (int j = 0; j < 8; j++)
                    acc[i * 8 + j] = fmaf(af[i], bf[j], acc[i * 8 + j]);
        }
        if (c < 7) {
            storeChunk((c + 1) & 1);
            __syncthreads();
        }
    }

    float bj[8];
#pragma unroll
    for (int j = 0; j < 8; j++) bj[j] = bias[tx * 8 + j];

    float lsum[8], lsq[8];
#pragma unroll
    for (int j = 0; j < 8; j++) { lsum[j] = 0.f; lsq[j] = 0.f; }

#pragma unroll
    for (int i = 0; i < 8; i++) {
        int row = rowBase + ty * 8 + i;
        if (row < M) {
            float v[8];
#pragma unroll
            for (int j = 0; j < 8; j++) {
                v[j] = acc[i * 8 + j] + bj[j];
                lsum[j] += v[j];
                lsq[j] = fmaf(v[j], v[j], lsq[j]);
            }
            float4* zp = (float4*)(Z + (size_t)row * DD + tx * 8);
            zp[0] = make_float4(v[0], v[1], v[2], v[3]);
            zp[1] = make_float4(v[4], v[5], v[6], v[7]);
        }
    }
#pragma unroll
    for (int j = 0; j < 8; j++) {
        atomicAdd(&csum[tx * 8 + j], lsum[j]);
        atomicAdd(&csq[tx * 8 + j], lsq[j]);
    }
    __syncthreads();
    if (tid < DD) {
        atomicAdd(&gsum[tid], csum[tid]);
        atomicAdd(&gsq[tid], csq[tid]);
    }
}

// ---------------------------------------------------------------- BN finalize
__global__ void finalize_kernel(float* __restrict__ gsum, float* __restrict__ gsq,
                                const float* __restrict__ gamma, const float* __restrict__ beta,
                                float invM, float* __restrict__ sOut, float* __restrict__ cOut) {
    int j = threadIdx.x;
    float mean = gsum[j] * invM;
    float var = gsq[j] * invM - mean * mean;
    float s = gamma[j] * rsqrtf(var + 1e-5f);
    sOut[j] = s;
    cOut[j] = beta[j] - mean * s;
    gsum[j] = 0.f;
    gsq[j] = 0.f;
}

// ---------------------------------------------------------------- final apply
__global__ void apply_kernel(const float4* __restrict__ z, const float* __restrict__ s,
                             const float* __restrict__ c, float4* __restrict__ out, int n4) {
    int i = blockIdx.x * blockDim.x + threadIdx.x;
    if (i >= n4) return;
    int k = (i & 31) * 4;
    float4 v = z[i];
    out[i] = make_float4(fmaf(s[k + 0], v.x, c[k + 0]),
                         fmaf(s[k + 1], v.y, c[k + 1]),
                         fmaf(s[k + 2], v.z, c[k + 2]),
                         fmaf(s[k + 3], v.w, c[k + 3]));
}

// ---------------------------------------------------------------- launch
extern "C" void kernel_launch(void* const* d_in, const int* in_sizes, int n_in,
                              void* d_out, int out_size) {
    const float* x    = (const float*)d_in[0];
    const void*  ei   = d_in[1];
    const float* W1   = (const float*)d_in[2];
    const float* b1   = (const float*)d_in[3];
    const float* g1   = (const float*)d_in[4];
    const float* bt1  = (const float*)d_in[5];
    const float* W2   = (const float*)d_in[6];
    const float* b2   = (const float*)d_in[7];
    const float* epsv = (const float*)d_in[8];
    const float* gout = (const float*)d_in[9];
    const float* bout = (const float*)d_in[10];

    int N = in_sizes[0] / DD;
    int E = in_sizes[1] / 2;

    void* p;
    cudaGetSymbolAddress(&p, g_aggr); float* aggr = (float*)p;
    cudaGetSymbolAddress(&p, g_z1);   float* z1   = (float*)p;
    cudaGetSymbolAddress(&p, g_z2);   float* z2   = (float*)p;
    cudaGetSymbolAddress(&p, g_idx);  int*   idx  = (int*)p;
    cudaGetSymbolAddress(&p, g_sum);  float* gsum = (float*)p;
    cudaGetSymbolAddress(&p, g_sq);   float* gsq  = (float*)p;
    cudaGetSymbolAddress(&p, g_s1);   float* s1   = (float*)p;
    cudaGetSymbolAddress(&p, g_c1);   float* c1   = (float*)p;
    cudaGetSymbolAddress(&p, g_sh);   float* sh   = (float*)p;
    cudaGetSymbolAddress(&p, g_ch);   float* ch   = (float*)p;

    constexpr int SMEM = (128 * WPAD + 2 * 16 * WPAD + 2 * DD) * 4;
    cudaFuncSetAttribute(gemm_kernel, cudaFuncAttributeMaxDynamicSharedMemorySize, SMEM);

    float invM = 1.0f / (float)N;
    int n4 = N * (DD / 4);
    int zb = (n4 + 255) / 256;
    long long sthreads = (long long)E * 32;
    int sb = (int)((sthreads + 255) / 256);
    int gb = (N + 127) / 128;
    int n2 = 2 * E;
    int cb = (n2 + 255) / 256;

    // canonicalize edge indices (handles int32- or int64-delivered edge_index)
    detect_kernel<<<1, 1>>>((const int*)ei, E);
    convert_kernel<<<cb, 256>>>(ei, n2, N);

    // ---- layer 0 ----
    zero_kernel<<<zb, 256>>>((float4*)aggr, n4);
    scatter_kernel<<<sb, 256>>>((const float4*)x, idx, E, aggr, nullptr, nullptr, 0);
    gemm_kernel<<<gb, 256, SMEM>>>(x, aggr, W1, b1, nullptr, nullptr, epsv, 0, 0, N, z1, gsum, gsq);
    finalize_kernel<<<1, DD>>>(gsum, gsq, g1, bt1, invM, s1, c1);
    gemm_kernel<<<gb, 256, SMEM>>>(z1, nullptr, W2, b2, s1, c1, epsv, 0, 2, N, z2, gsum, gsq);
    finalize_kernel<<<1, DD>>>(gsum, gsq, gout, bout, invM, sh, ch);

    // ---- layer 1 ----
    zero_kernel<<<zb, 256>>>((float4*)aggr, n4);
    scatter_kernel<<<sb, 256>>>((const float4*)z2, idx, E, aggr, sh, ch, 1);
    gemm_kernel<<<gb, 256, SMEM>>>(z2, aggr, W1 + DD * DD, b1 + DD, sh, ch, epsv, 1, 1, N, z1, gsum, gsq);
    finalize_kernel<<<1, DD>>>(gsum, gsq, g1 + DD, bt1 + DD, invM, s1, c1);
    gemm_kernel<<<gb, 256, SMEM>>>(z1, nullptr, W2 + DD * DD, b2 + DD, s1, c1, epsv, 1, 2, N, z2, gsum, gsq);
    finalize_kernel<<<1, DD>>>(gsum, gsq, gout + DD, bout + DD, invM, sh, ch);

    apply_kernel<<<zb, 256>>>((const float4*)z2, sh, ch, (float4*)d_out, n4);
}

// round 5
// speedup vs baseline: 1.2428x; 1.2428x over previous
#include <cuda_runtime.h>
#include <cuda_bf16.h>
#include <cstddef>

#define DD 128
#define MAXN 100000
#define MAXE 1000000
#define WPAD 132   // smem row stride: %4==0 -> 16B-aligned rows for LDS.128; not %32 -> de-conflicted banks

// ---- scratch (no cudaMalloc allowed) ----
__device__ float g_aggr[(size_t)MAXN * DD];
__device__ float g_z1[(size_t)MAXN * DD];
__device__ float g_z2[(size_t)MAXN * DD];
__device__ int   g_idx[(size_t)2 * MAXE];   // canonical int32 edge list: [src(E), dst(E)]
__device__ int   g_fmt;                      // 1 = input was int64, 0 = int32
__device__ float g_sum[DD];
__device__ float g_sq[DD];
__device__ float g_s1[DD];
__device__ float g_c1[DD];
__device__ float g_sh[DD];
__device__ float g_ch[DD];

// ---------------------------------------------------------------- edge fmt detect
__global__ void detect_kernel(const int* __restrict__ ei32, int E) {
    int allzero = 1;
    for (int k = 0; k < 64; k++) {
        long long e = (long long)(k + 1) * (2LL * E) / 66;
        if (ei32[2 * (e >> 1) + 1] != 0) { allzero = 0; break; }
    }
    g_fmt = allzero;
}

__global__ void convert_kernel(const void* __restrict__ ei, int n2, int N) {
    int i = blockIdx.x * blockDim.x + threadIdx.x;
    if (i >= n2) return;
    int v;
    if (g_fmt) v = (int)((const long long*)ei)[i];
    else       v = ((const int*)ei)[i];
    if (v < 0) v = 0;
    if (v >= N) v = N - 1;
    g_idx[i] = v;
}

// ---------------------------------------------------------------- aggr init
// mode 0: aggr = ev * h                       (layer 0, h = x)
// mode 1: aggr = ev * relu(s*h + c)           (layer 1, h = z2, affine = outer BN)
__global__ void init_kernel(const float4* __restrict__ h, float4* __restrict__ aggr,
                            const float* __restrict__ s, const float* __restrict__ c,
                            const float* __restrict__ epsP, int layer, int mode, int n4) {
    int i = blockIdx.x * blockDim.x + threadIdx.x;
    if (i >= n4) return;
    float ev = 1.0f + epsP[layer];
    float4 v = h[i];
    if (mode) {
        int k = (i & 31) * 4;
        v.x = fmaxf(fmaf(s[k + 0], v.x, c[k + 0]), 0.f);
        v.y = fmaxf(fmaf(s[k + 1], v.y, c[k + 1]), 0.f);
        v.z = fmaxf(fmaf(s[k + 2], v.z, c[k + 2]), 0.f);
        v.w = fmaxf(fmaf(s[k + 3], v.w, c[k + 3]), 0.f);
    }
    aggr[i] = make_float4(ev * v.x, ev * v.y, ev * v.z, ev * v.w);
}

// ---------------------------------------------------------------- scatter
// mode 0: msg = relu(h[src])
// mode 1: msg = relu(sH*h[src]+cH)
// Accumulate into aggr via vectorized red.global.add.v4.f32 (coalesced 512B per warp).
__global__ void scatter_kernel(const float4* __restrict__ h,
                               const int* __restrict__ idx, int E,
                               float* __restrict__ aggr,
                               const float* __restrict__ sH,
                               const float* __restrict__ cH, int mode) {
    __shared__ float ss[DD], sc[DD];
    if (mode) {
        if (threadIdx.x < DD) { ss[threadIdx.x] = sH[threadIdx.x]; sc[threadIdx.x] = cH[threadIdx.x]; }
        __syncthreads();
    }
    int gt = blockIdx.x * blockDim.x + threadIdx.x;
    int e = gt >> 5;
    if (e >= E) return;
    int lane = gt & 31;
    int src = idx[e];
    int dst = idx[E + e];
    float4 v = h[(size_t)src * 32 + lane];
    int k = lane * 4;
    if (mode) {
        v.x = fmaf(ss[k + 0], v.x, sc[k + 0]);
        v.y = fmaf(ss[k + 1], v.y, sc[k + 1]);
        v.z = fmaf(ss[k + 2], v.z, sc[k + 2]);
        v.w = fmaf(ss[k + 3], v.w, sc[k + 3]);
    }
    v.x = fmaxf(v.x, 0.f); v.y = fmaxf(v.y, 0.f);
    v.z = fmaxf(v.z, 0.f); v.w = fmaxf(v.w, 0.f);
    if (v.x != 0.f || v.y != 0.f || v.z != 0.f || v.w != 0.f) {
        float* o = aggr + (size_t)dst * DD + k;
        asm volatile("red.global.add.v4.f32 [%0], {%1, %2, %3, %4};"
                     :: "l"(o), "f"(v.x), "f"(v.y), "f"(v.z), "f"(v.w) : "memory");
    }
}

// ---------------------------------------------------------------- GEMM
// out[row][j] = sum_k a(row,k) * W[j][k] + bias[j]
// mode 0: a = Ab                      (gemm1: Ab = aggr already holds (1+eps)h + msgs)
// mode 2: a = relu(sIn*Ab+cIn)        (gemm2: Ab = z1, affine = inner BN)
// Epilogue: write Z, accumulate per-feature sum & sumsq.
__global__ void __launch_bounds__(256, 2) gemm_kernel(
    const float* __restrict__ Ab,
    const float* __restrict__ W, const float* __restrict__ bias,
    const float* __restrict__ sIn, const float* __restrict__ cIn,
    int mode, int M,
    float* __restrict__ Z, float* __restrict__ gsum, float* __restrict__ gsq) {
    extern __shared__ float sm[];
    float* Ws = sm;                    // 128*WPAD (transposed: Ws[k*WPAD+j] = W[j][k])
    float* As = Ws + 128 * WPAD;       // 2 * 16 * WPAD
    float* csum = As + 2 * 16 * WPAD;  // 128
    float* csq = csum + DD;            // 128

    const int tid = threadIdx.x;
    for (int i = tid; i < DD * DD; i += 256) {
        int j = i >> 7, k = i & 127;
        Ws[k * WPAD + j] = W[i];
    }
    if (tid < DD) { csum[tid] = 0.f; csq[tid] = 0.f; }

    const int tx = tid & 15, ty = tid >> 4;
    const int rowBase = blockIdx.x << 7;

    const int m0 = tid >> 2;
    const int kq = tid & 3;

    float acc[64];
#pragma unroll
    for (int i = 0; i < 64; i++) acc[i] = 0.f;

    float4 ra[2];

    auto loadChunk = [&](int c) {
        int kbase = c * 16 + kq * 4;
#pragma unroll
        for (int h2 = 0; h2 < 2; h2++) {
            int row = rowBase + m0 + h2 * 64;
            float4 v = make_float4(0.f, 0.f, 0.f, 0.f);
            if (row < M) {
                v = *(const float4*)(Ab + (size_t)row * DD + kbase);
                if (mode == 2) {
                    v.x = fmaxf(fmaf(sIn[kbase + 0], v.x, cIn[kbase + 0]), 0.f);
                    v.y = fmaxf(fmaf(sIn[kbase + 1], v.y, cIn[kbase + 1]), 0.f);
                    v.z = fmaxf(fmaf(sIn[kbase + 2], v.z, cIn[kbase + 2]), 0.f);
                    v.w = fmaxf(fmaf(sIn[kbase + 3], v.w, cIn[kbase + 3]), 0.f);
                }
            }
            ra[h2] = v;
        }
    };
    auto storeChunk = [&](int buf) {
        float* p = As + buf * (16 * WPAD);
#pragma unroll
        for (int h2 = 0; h2 < 2; h2++) {
            int m = m0 + h2 * 64;
            p[(kq * 4 + 0) * WPAD + m] = ra[h2].x;
            p[(kq * 4 + 1) * WPAD + m] = ra[h2].y;
            p[(kq * 4 + 2) * WPAD + m] = ra[h2].z;
            p[(kq * 4 + 3) * WPAD + m] = ra[h2].w;
        }
    };

    loadChunk(0);
    storeChunk(0);
    __syncthreads();

    for (int c = 0; c < 8; c++) {
        if (c < 7) loadChunk(c + 1);
        float* pA = As + (c & 1) * (16 * WPAD);
#pragma unroll
        for (int kk = 0; kk < 16; kk++) {
            float af[8], bf[8];
            *(float4*)(af)     = *(const float4*)(pA + kk * WPAD + ty * 8);
            *(float4*)(af + 4) = *(const float4*)(pA + kk * WPAD + ty * 8 + 4);
            int kg = c * 16 + kk;
            *(float4*)(bf)     = *(const float4*)(Ws + kg * WPAD + tx * 8);
            *(float4*)(bf + 4) = *(const float4*)(Ws + kg * WPAD + tx * 8 + 4);
#pragma unroll
            for (int i = 0; i < 8; i++)
#pragma unroll
                for (int j = 0; j < 8; j++)
                    acc[i * 8 + j] = fmaf(af[i], bf[j], acc[i * 8 + j]);
        }
        if (c < 7) {
            storeChunk((c + 1) & 1);
            __syncthreads();
        }
    }

    float bj[8];
#pragma unroll
    for (int j = 0; j < 8; j++) bj[j] = bias[tx * 8 + j];

    float lsum[8], lsq[8];
#pragma unroll
    for (int j = 0; j < 8; j++) { lsum[j] = 0.f; lsq[j] = 0.f; }

#pragma unroll
    for (int i = 0; i < 8; i++) {
        int row = rowBase + ty * 8 + i;
        if (row < M) {
            float v[8];
#pragma unroll
            for (int j = 0; j < 8; j++) {
                v[j] = acc[i * 8 + j] + bj[j];
                lsum[j] += v[j];
                lsq[j] = fmaf(v[j], v[j], lsq[j]);
            }
            float4* zp = (float4*)(Z + (size_t)row * DD + tx * 8);
            zp[0] = make_float4(v[0], v[1], v[2], v[3]);
            zp[1] = make_float4(v[4], v[5], v[6], v[7]);
        }
    }
#pragma unroll
    for (int j = 0; j < 8; j++) {
        atomicAdd(&csum[tx * 8 + j], lsum[j]);
        atomicAdd(&csq[tx * 8 + j], lsq[j]);
    }
    __syncthreads();
    if (tid < DD) {
        atomicAdd(&gsum[tid], csum[tid]);
        atomicAdd(&gsq[tid], csq[tid]);
    }
}

// ---------------------------------------------------------------- BN finalize
__global__ void finalize_kernel(float* __restrict__ gsum, float* __restrict__ gsq,
                                const float* __restrict__ gamma, const float* __restrict__ beta,
                                float invM, float* __restrict__ sOut, float* __restrict__ cOut) {
    int j = threadIdx.x;
    float mean = gsum[j] * invM;
    float var = gsq[j] * invM - mean * mean;
    float s = gamma[j] * rsqrtf(var + 1e-5f);
    sOut[j] = s;
    cOut[j] = beta[j] - mean * s;
    gsum[j] = 0.f;
    gsq[j] = 0.f;
}

// ---------------------------------------------------------------- final apply
__global__ void apply_kernel(const float4* __restrict__ z, const float* __restrict__ s,
                             const float* __restrict__ c, float4* __restrict__ out, int n4) {
    int i = blockIdx.x * blockDim.x + threadIdx.x;
    if (i >= n4) return;
    int k = (i & 31) * 4;
    float4 v = z[i];
    out[i] = make_float4(fmaf(s[k + 0], v.x, c[k + 0]),
                         fmaf(s[k + 1], v.y, c[k + 1]),
                         fmaf(s[k + 2], v.z, c[k + 2]),
                         fmaf(s[k + 3], v.w, c[k + 3]));
}

// ---------------------------------------------------------------- launch
extern "C" void kernel_launch(void* const* d_in, const int* in_sizes, int n_in,
                              void* d_out, int out_size) {
    const float* x    = (const float*)d_in[0];
    const void*  ei   = d_in[1];
    const float* W1   = (const float*)d_in[2];
    const float* b1   = (const float*)d_in[3];
    const float* g1   = (const float*)d_in[4];
    const float* bt1  = (const float*)d_in[5];
    const float* W2   = (const float*)d_in[6];
    const float* b2   = (const float*)d_in[7];
    const float* epsv = (const float*)d_in[8];
    const float* gout = (const float*)d_in[9];
    const float* bout = (const float*)d_in[10];

    int N = in_sizes[0] / DD;
    int E = in_sizes[1] / 2;

    void* p;
    cudaGetSymbolAddress(&p, g_aggr); float* aggr = (float*)p;
    cudaGetSymbolAddress(&p, g_z1);   float* z1   = (float*)p;
    cudaGetSymbolAddress(&p, g_z2);   float* z2   = (float*)p;
    cudaGetSymbolAddress(&p, g_idx);  int*   idx  = (int*)p;
    cudaGetSymbolAddress(&p, g_sum);  float* gsum = (float*)p;
    cudaGetSymbolAddress(&p, g_sq);   float* gsq  = (float*)p;
    cudaGetSymbolAddress(&p, g_s1);   float* s1   = (float*)p;
    cudaGetSymbolAddress(&p, g_c1);   float* c1   = (float*)p;
    cudaGetSymbolAddress(&p, g_sh);   float* sh   = (float*)p;
    cudaGetSymbolAddress(&p, g_ch);   float* ch   = (float*)p;

    constexpr int SMEM = (128 * WPAD + 2 * 16 * WPAD + 2 * DD) * 4;
    cudaFuncSetAttribute(gemm_kernel, cudaFuncAttributeMaxDynamicSharedMemorySize, SMEM);

    float invM = 1.0f / (float)N;
    int n4 = N * (DD / 4);
    int zb = (n4 + 255) / 256;
    long long sthreads = (long long)E * 32;
    int sb = (int)((sthreads + 255) / 256);
    int gb = (N + 127) / 128;
    int n2 = 2 * E;
    int cb = (n2 + 255) / 256;

    // canonicalize edge indices (handles int32- or int64-delivered edge_index)
    detect_kernel<<<1, 1>>>((const int*)ei, E);
    convert_kernel<<<cb, 256>>>(ei, n2, N);

    // ---- layer 0 ----
    init_kernel<<<zb, 256>>>((const float4*)x, (float4*)aggr, nullptr, nullptr, epsv, 0, 0, n4);
    scatter_kernel<<<sb, 256>>>((const float4*)x, idx, E, aggr, nullptr, nullptr, 0);
    gemm_kernel<<<gb, 256, SMEM>>>(aggr, W1, b1, nullptr, nullptr, 0, N, z1, gsum, gsq);
    finalize_kernel<<<1, DD>>>(gsum, gsq, g1, bt1, invM, s1, c1);
    gemm_kernel<<<gb, 256, SMEM>>>(z1, W2, b2, s1, c1, 2, N, z2, gsum, gsq);
    finalize_kernel<<<1, DD>>>(gsum, gsq, gout, bout, invM, sh, ch);

    // ---- layer 1 ----
    init_kernel<<<zb, 256>>>((const float4*)z2, (float4*)aggr, sh, ch, epsv, 1, 1, n4);
    scatter_kernel<<<sb, 256>>>((const float4*)z2, idx, E, aggr, sh, ch, 1);
    gemm_kernel<<<gb, 256, SMEM>>>(aggr, W1 + DD * DD, b1 + DD, nullptr, nullptr, 0, N, z1, gsum, gsq);
    finalize_kernel<<<1, DD>>>(gsum, gsq, g1 + DD, bt1 + DD, invM, s1, c1);
    gemm_kernel<<<gb, 256, SMEM>>>(z1, W2 + DD * DD, b2 + DD, s1, c1, 2, N, z2, gsum, gsq);
    finalize_kernel<<<1, DD>>>(gsum, gsq, gout + DD, bout + DD, invM, sh, ch);

    apply_kernel<<<zb, 256>>>((const float4*)z2, sh, ch, (float4*)d_out, n4);
}